// round 2
// baseline (speedup 1.0000x reference)
// AttLayer fused kernel for GB300 (sm_103a, but PTX target is plain sm_103:
// NO tcgen05/TMEM — use mma.sync tf32 (legacy HMMA path) + cp.async).
// out[b,d] = sum_t exp(tanh(x@W + b)·uw)_t * x[b,t,d] / (sum_t exp(...) + eps)
// x tile [128,256] fp32 resident in SMEM: A-operand for tf32 MMA AND exact
// fp32 source for the weighted-sum epilogue. W streamed in 8 double-buffered
// K-chunks of 32 via cp.async. Deterministic 2-kernel reduction.

#include <cuda_runtime.h>
#include <cstdint>
#include <math.h>

#define DEV __device__ __forceinline__

static constexpr int BATCH  = 64;
static constexpr int TLEN   = 2048;
static constexpr int DIM    = 256;
static constexpr int TILE_T = 128;
static constexpr int NTILES = TLEN / TILE_T;   // 16
static constexpr int KC     = 32;              // K per chunk
static constexpr int NCHUNK = DIM / KC;        // 8

static constexpr int XSTR   = DIM + 4;         // 260 floats: conflict-free strides

// SMEM layout (floats / bytes)
static constexpr int SMEM_BIAS = 0;                        // 256 f
static constexpr int SMEM_UW   = 1024;                     // 256 f
static constexpr int SMEM_EP   = 2048;                     // 128*4 f = 2048B
static constexpr int SMEM_WEXP = 4096;                     // 128 f
static constexpr int SMEM_X    = 5120;                     // 128*260*4 = 133120
static constexpr int SMEM_W    = SMEM_X + TILE_T * XSTR * 4;       // 138240
static constexpr int W_CHUNK_B = KC * XSTR * 4;                    // 33280
static constexpr int SMEM_TOTAL = SMEM_W + 2 * W_CHUNK_B;          // 204800

__device__ float g_partial[BATCH * NTILES * DIM];
__device__ float g_S[BATCH * NTILES];

DEV uint32_t smem_u32(const void* p) {
    uint32_t a;
    asm("{ .reg .u64 t; cvta.to.shared.u64 t, %1; cvt.u32.u64 %0, t; }"
        : "=r"(a) : "l"(p));
    return a;
}
DEV void cp16(uint32_t saddr, const void* g) {
    asm volatile("cp.async.cg.shared.global [%0], [%1], 16;"
                 :: "r"(saddr), "l"(g) : "memory");
}
DEV void cp_commit() { asm volatile("cp.async.commit_group;" ::: "memory"); }
template <int N> DEV void cp_wait() {
    asm volatile("cp.async.wait_group %0;" :: "n"(N) : "memory");
}
DEV uint32_t f2tf(float f) {
    uint32_t r;
    asm("cvt.rna.tf32.f32 %0, %1;" : "=r"(r) : "f"(f));
    return r;
}
DEV void mma_tf32(float* d, uint32_t a0, uint32_t a1, uint32_t a2, uint32_t a3,
                  uint32_t b0, uint32_t b1) {
    asm volatile(
        "mma.sync.aligned.m16n8k8.row.col.f32.tf32.tf32.f32 "
        "{%0,%1,%2,%3}, {%4,%5,%6,%7}, {%8,%9}, {%0,%1,%2,%3};"
        : "+f"(d[0]), "+f"(d[1]), "+f"(d[2]), "+f"(d[3])
        : "r"(a0), "r"(a1), "r"(a2), "r"(a3), "r"(b0), "r"(b1));
}

__global__ void __launch_bounds__(512, 1)
att_main(const float* __restrict__ x, const float* __restrict__ W,
         const float* __restrict__ bvec, const float* __restrict__ uw,
         const int* __restrict__ mask) {
    extern __shared__ char smem[];
    float* sf = (float*)smem;
    const uint32_t sb = smem_u32(smem);

    const int tid = threadIdx.x;
    const int wid = tid >> 5;
    const int lid = tid & 31;
    const int wm  = wid >> 2;            // 0..3 : rows wm*32..wm*32+31
    const int wn  = wid & 3;             // 0..3 : cols wn*64..wn*64+63
    const int g   = lid >> 2;            // groupID 0..7
    const int tg  = lid & 3;             // threadInGroup 0..3

    const int bt = blockIdx.x;           // 0..1023
    const int b  = bt >> 4;
    const int t0 = (bt & 15) * TILE_T;

    // bias / uw to smem
    if (tid < 256) {
        sf[SMEM_BIAS / 4 + tid] = bvec[tid];
        sf[SMEM_UW / 4 + tid]   = uw[tid];
    }

    // ---- async loads: W chunk0 | x tile | W chunk1 ----
    const float* xrow = x + ((size_t)b * TLEN + t0) * DIM;
    {   // W chunk 0 -> buf 0  (2048 float4 / 512 thr = 4 each)
        for (int i = tid; i < KC * (DIM / 4); i += 512) {
            int k = i >> 6, n0 = (i & 63) * 4;
            cp16(sb + SMEM_W + (k * XSTR + n0) * 4, W + (size_t)k * DIM + n0);
        }
        cp_commit();
        // x tile (8192 float4 / 512 = 16 each)
        for (int i = tid; i < TILE_T * (DIM / 4); i += 512) {
            int m = i >> 6, d0 = (i & 63) * 4;
            cp16(sb + SMEM_X + (m * XSTR + d0) * 4, xrow + (size_t)m * DIM + d0);
        }
        cp_commit();
        // W chunk 1 -> buf 1
        for (int i = tid; i < KC * (DIM / 4); i += 512) {
            int k = i >> 6, n0 = (i & 63) * 4;
            cp16(sb + SMEM_W + W_CHUNK_B + (k * XSTR + n0) * 4,
                 W + (size_t)(KC + k) * DIM + n0);
        }
        cp_commit();
    }
    cp_wait<1>();        // chunk0 + x ready
    __syncthreads();

    // ---- mainloop ----
    float acc[2][8][4];
    #pragma unroll
    for (int i = 0; i < 2; ++i)
        #pragma unroll
        for (int j = 0; j < 8; ++j)
            #pragma unroll
            for (int r = 0; r < 4; ++r) acc[i][j][r] = 0.f;

    const float* xs = sf + SMEM_X / 4;
    const int arow0 = wm * 32 + g;

    for (int c = 0; c < NCHUNK; ++c) {
        const float* wb = sf + (SMEM_W + (c & 1) * W_CHUNK_B) / 4;
        #pragma unroll
        for (int s = 0; s < 4; ++s) {
            const int kc0 = s * 8 + tg;
            // A frags (2 m-tiles)
            uint32_t a[2][4];
            #pragma unroll
            for (int i = 0; i < 2; ++i) {
                const float* ar = xs + (arow0 + i * 16) * XSTR + c * KC + kc0;
                a[i][0] = f2tf(ar[0]);
                a[i][1] = f2tf(ar[8 * XSTR]);
                a[i][2] = f2tf(ar[4]);
                a[i][3] = f2tf(ar[8 * XSTR + 4]);
            }
            // B frags (8 n-tiles)
            uint32_t bfr[8][2];
            const float* br = wb + kc0 * XSTR + wn * 64 + g;
            #pragma unroll
            for (int j = 0; j < 8; ++j) {
                bfr[j][0] = f2tf(br[j * 8]);
                bfr[j][1] = f2tf(br[4 * XSTR + j * 8]);
            }
            #pragma unroll
            for (int i = 0; i < 2; ++i)
                #pragma unroll
                for (int j = 0; j < 8; ++j)
                    mma_tf32(acc[i][j], a[i][0], a[i][1], a[i][2], a[i][3],
                             bfr[j][0], bfr[j][1]);
        }
        __syncthreads();                         // done reading buf c&1
        if (c + 2 < NCHUNK) {                    // prefetch chunk c+2 into buf c&1
            const float* wsrc = W + (size_t)(c + 2) * KC * DIM;
            const uint32_t dst = sb + SMEM_W + (c & 1) * W_CHUNK_B;
            for (int i = tid; i < KC * (DIM / 4); i += 512) {
                int k = i >> 6, n0 = (i & 63) * 4;
                cp16(dst + (k * XSTR + n0) * 4, wsrc + (size_t)k * DIM + n0);
            }
            cp_commit();
        }
        if (c + 1 < NCHUNK) {
            if (c + 2 < NCHUNK) cp_wait<1>(); else cp_wait<0>();
            __syncthreads();
        }
    }

    // ---- epilogue 1: eij partials ----
    {
        const float* sBias = sf + SMEM_BIAS / 4;
        const float* sUw   = sf + SMEM_UW / 4;
        float* epart       = sf + SMEM_EP / 4;
        #pragma unroll
        for (int i = 0; i < 2; ++i) {
            float rs0 = 0.f, rs1 = 0.f;
            #pragma unroll
            for (int j = 0; j < 8; ++j) {
                const int c0 = wn * 64 + j * 8 + 2 * tg;
                const float b0 = sBias[c0], b1 = sBias[c0 + 1];
                const float u0 = sUw[c0],   u1 = sUw[c0 + 1];
                rs0 += tanhf(acc[i][j][0] + b0) * u0 + tanhf(acc[i][j][1] + b1) * u1;
                rs1 += tanhf(acc[i][j][2] + b0) * u0 + tanhf(acc[i][j][3] + b1) * u1;
            }
            rs0 += __shfl_xor_sync(0xFFFFFFFFu, rs0, 1);
            rs0 += __shfl_xor_sync(0xFFFFFFFFu, rs0, 2);
            rs1 += __shfl_xor_sync(0xFFFFFFFFu, rs1, 1);
            rs1 += __shfl_xor_sync(0xFFFFFFFFu, rs1, 2);
            if (tg == 0) {
                const int r = wm * 32 + i * 16 + g;
                epart[r * 4 + wn]       = rs0;
                epart[(r + 8) * 4 + wn] = rs1;
            }
        }
    }
    __syncthreads();

    // ---- epilogue 2: weights ----
    float* sWexp = sf + SMEM_WEXP / 4;
    if (tid < TILE_T) {
        const float* epart = sf + SMEM_EP / 4;
        float e = epart[tid * 4 + 0] + epart[tid * 4 + 1] +
                  epart[tid * 4 + 2] + epart[tid * 4 + 3];
        sWexp[tid] = expf(e) * (float)mask[(size_t)b * TLEN + t0 + tid];
    }
    __syncthreads();

    if (tid == 0) {
        float s = 0.f;
        #pragma unroll 8
        for (int m = 0; m < TILE_T; ++m) s += sWexp[m];
        g_S[bt] = s;
    }

    // ---- epilogue 3: weighted column sum from resident fp32 x tile ----
    if (tid < DIM) {
        float a0 = 0.f;
        #pragma unroll 8
        for (int m = 0; m < TILE_T; ++m)
            a0 = fmaf(sWexp[m], xs[m * XSTR + tid], a0);
        g_partial[(size_t)bt * DIM + tid] = a0;
    }
}

__global__ void att_norm(float* __restrict__ out) {
    const int b = blockIdx.x;
    const int d = threadIdx.x;
    float p = 0.f, s = 0.f;
    #pragma unroll
    for (int t = 0; t < NTILES; ++t) {
        p += g_partial[(size_t)(b * NTILES + t) * DIM + d];
        s += g_S[b * NTILES + t];
    }
    out[b * DIM + d] = p / (s + 1e-7f);
}

extern "C" void kernel_launch(void* const* d_in, const int* in_sizes, int n_in,
                              void* d_out, int out_size) {
    const float* x    = (const float*)d_in[0];
    const float* W    = (const float*)d_in[1];
    const float* bvec = (const float*)d_in[2];
    const float* uw   = (const float*)d_in[3];
    const int*   mask = (const int*)d_in[4];
    float* out = (float*)d_out;

    cudaFuncSetAttribute(att_main, cudaFuncAttributeMaxDynamicSharedMemorySize,
                         SMEM_TOTAL);
    att_main<<<BATCH * NTILES, 512, SMEM_TOTAL>>>(x, W, bvec, uw, mask);
    att_norm<<<BATCH, DIM>>>(out);
}

// round 4
// speedup vs baseline: 1.0576x; 1.0576x over previous
// AttLayer fused single-kernel for GB300 (sm_103 PTX target: mma.sync tf32 + cp.async).
// out[b,d] = sum_t exp(tanh(x@W + b)·uw)_t * x[b,t,d] / (sum_t exp(...) + eps)
// R2: fused tail reduction (atomic counter, fixed-order deterministic sum),
//     quad-buffered W (KC=16, prefetch distance 3), W stride 264 (bank-conflict-free).

#include <cuda_runtime.h>
#include <cstdint>
#include <math.h>

#define DEV __device__ __forceinline__

static constexpr int BATCH  = 64;
static constexpr int TLEN   = 2048;
static constexpr int DIM    = 256;
static constexpr int TILE_T = 128;
static constexpr int NTILES = TLEN / TILE_T;   // 16
static constexpr int KC     = 16;              // K per chunk
static constexpr int NCHUNK = DIM / KC;        // 16
static constexpr int NBUF   = 4;               // W ring buffers

static constexpr int XSTR   = 260;             // x row stride (floats), A-frags conflict-free
static constexpr int WSTR   = 264;             // W row stride (floats), ≡8 mod 32 -> B-frags conflict-free

// SMEM layout (bytes)
static constexpr int SMEM_BIAS = 0;                              // 256 f
static constexpr int SMEM_UW   = 1024;                           // 256 f
static constexpr int SMEM_EP   = 2048;                           // 128*4 f
static constexpr int SMEM_WEXP = 4096;                           // 128 f
static constexpr int SMEM_FLAG = 4608;                           // int
static constexpr int SMEM_X    = 4864;
static constexpr int X_BYTES   = TILE_T * XSTR * 4;              // 133120
static constexpr int SMEM_W    = SMEM_X + X_BYTES;               // 137984
static constexpr int W_CHUNK_B = KC * WSTR * 4;                  // 16896
static constexpr int SMEM_TOTAL = SMEM_W + NBUF * W_CHUNK_B;     // 205568

__device__ float g_partial[BATCH * NTILES * DIM];
__device__ float g_S[BATCH * NTILES];
__device__ int   g_cnt[BATCH];   // zero-initialized; reset by reducer each call

DEV uint32_t smem_u32(const void* p) {
    uint32_t a;
    asm("{ .reg .u64 t; cvta.to.shared.u64 t, %1; cvt.u32.u64 %0, t; }"
        : "=r"(a) : "l"(p));
    return a;
}
DEV void cp16(uint32_t saddr, const void* g) {
    asm volatile("cp.async.cg.shared.global [%0], [%1], 16;"
                 :: "r"(saddr), "l"(g) : "memory");
}
DEV void cp_commit() { asm volatile("cp.async.commit_group;" ::: "memory"); }
template <int N> DEV void cp_wait() {
    asm volatile("cp.async.wait_group %0;" :: "n"(N) : "memory");
}
DEV uint32_t f2tf(float f) {
    uint32_t r;
    asm("cvt.rna.tf32.f32 %0, %1;" : "=r"(r) : "f"(f));
    return r;
}
DEV void mma_tf32(float* d, uint32_t a0, uint32_t a1, uint32_t a2, uint32_t a3,
                  uint32_t b0, uint32_t b1) {
    asm volatile(
        "mma.sync.aligned.m16n8k8.row.col.f32.tf32.tf32.f32 "
        "{%0,%1,%2,%3}, {%4,%5,%6,%7}, {%8,%9}, {%0,%1,%2,%3};"
        : "+f"(d[0]), "+f"(d[1]), "+f"(d[2]), "+f"(d[3])
        : "r"(a0), "r"(a1), "r"(a2), "r"(a3), "r"(b0), "r"(b1));
}

DEV void load_w_chunk(uint32_t sb, const float* __restrict__ W, int c, int buf, int tid) {
    // W rows c*KC .. c*KC+15, all 256 cols, into ring buffer `buf`
    const float* wsrc = W + (size_t)c * KC * DIM;
    const uint32_t dst = sb + (uint32_t)(SMEM_W + buf * W_CHUNK_B);
    // 16*64 = 1024 float4 / 512 threads = 2 each
    #pragma unroll
    for (int r = 0; r < 2; ++r) {
        int i = tid + r * 512;
        int k = i >> 6, n0 = (i & 63) * 4;
        cp16(dst + (uint32_t)(k * WSTR + n0) * 4, wsrc + (size_t)k * DIM + n0);
    }
    cp_commit();
}

__global__ void __launch_bounds__(512, 1)
att_fused(const float* __restrict__ x, const float* __restrict__ W,
          const float* __restrict__ bvec, const float* __restrict__ uw,
          const int* __restrict__ mask, float* __restrict__ out) {
    extern __shared__ char smem[];
    float* sf = (float*)smem;
    const uint32_t sb = smem_u32(smem);

    const int tid = threadIdx.x;
    const int wid = tid >> 5;
    const int lid = tid & 31;
    const int wm  = wid >> 2;            // 0..3 : rows wm*32..+31
    const int wn  = wid & 3;             // 0..3 : cols wn*64..+63
    const int g   = lid >> 2;            // 0..7
    const int tg  = lid & 3;             // 0..3

    const int bt = blockIdx.x;           // 0..1023
    const int b  = bt >> 4;
    const int t0 = (bt & 15) * TILE_T;

    if (tid < 256) {
        sf[SMEM_BIAS / 4 + tid] = bvec[tid];
        sf[SMEM_UW / 4 + tid]   = uw[tid];
    }

    // ---- prologue: W0 | x | W1 | W2 | W3 (5 cp.async groups) ----
    const float* xrow = x + ((size_t)b * TLEN + t0) * DIM;
    load_w_chunk(sb, W, 0, 0, tid);
    {   // x tile (8192 float4 / 512 = 16 each)
        #pragma unroll
        for (int r = 0; r < 16; ++r) {
            int i = tid + r * 512;
            int m = i >> 6, d0 = (i & 63) * 4;
            cp16(sb + SMEM_X + (uint32_t)(m * XSTR + d0) * 4,
                 xrow + (size_t)m * DIM + d0);
        }
        cp_commit();
    }
    load_w_chunk(sb, W, 1, 1, tid);
    load_w_chunk(sb, W, 2, 2, tid);
    load_w_chunk(sb, W, 3, 3, tid);
    cp_wait<3>();            // W0 + x ready
    __syncthreads();

    // ---- mainloop ----
    float acc[2][8][4];
    #pragma unroll
    for (int i = 0; i < 2; ++i)
        #pragma unroll
        for (int j = 0; j < 8; ++j)
            #pragma unroll
            for (int r = 0; r < 4; ++r) acc[i][j][r] = 0.f;

    const float* xs = sf + SMEM_X / 4;
    const int arow0 = wm * 32 + g;

    for (int c = 0; c < NCHUNK; ++c) {
        const float* wb = sf + (SMEM_W + (c & (NBUF - 1)) * W_CHUNK_B) / 4;
        #pragma unroll
        for (int s = 0; s < 2; ++s) {          // KC=16 -> 2 k8 steps
            const int kc0 = s * 8 + tg;
            uint32_t a[2][4];
            #pragma unroll
            for (int i = 0; i < 2; ++i) {
                const float* ar = xs + (arow0 + i * 16) * XSTR + c * KC + kc0;
                a[i][0] = f2tf(ar[0]);
                a[i][1] = f2tf(ar[8 * XSTR]);
                a[i][2] = f2tf(ar[4]);
                a[i][3] = f2tf(ar[8 * XSTR + 4]);
            }
            uint32_t bfr[8][2];
            const float* br = wb + kc0 * WSTR + wn * 64 + g;
            #pragma unroll
            for (int j = 0; j < 8; ++j) {
                bfr[j][0] = f2tf(br[j * 8]);
                bfr[j][1] = f2tf(br[4 * WSTR + j * 8]);
            }
            #pragma unroll
            for (int i = 0; i < 2; ++i)
                #pragma unroll
                for (int j = 0; j < 8; ++j)
                    mma_tf32(acc[i][j], a[i][0], a[i][1], a[i][2], a[i][3],
                             bfr[j][0], bfr[j][1]);
        }
        __syncthreads();                       // everyone done reading buf c%4
        if (c + NBUF < NCHUNK)
            load_w_chunk(sb, W, c + NBUF, c & (NBUF - 1), tid);
        if (c + 4 < NCHUNK)      cp_wait<3>();
        else if (c + 3 < NCHUNK) cp_wait<2>();
        else if (c + 2 < NCHUNK) cp_wait<1>();
        else if (c + 1 < NCHUNK) cp_wait<0>();
        if (c + 1 < NCHUNK) __syncthreads();
    }

    // ---- epilogue 1: eij partials ----
    {
        const float* sBias = sf + SMEM_BIAS / 4;
        const float* sUw   = sf + SMEM_UW / 4;
        float* epart       = sf + SMEM_EP / 4;
        #pragma unroll
        for (int i = 0; i < 2; ++i) {
            float rs0 = 0.f, rs1 = 0.f;
            #pragma unroll
            for (int j = 0; j < 8; ++j) {
                const int c0 = wn * 64 + j * 8 + 2 * tg;
                const float b0 = sBias[c0], b1 = sBias[c0 + 1];
                const float u0 = sUw[c0],   u1 = sUw[c0 + 1];
                rs0 += tanhf(acc[i][j][0] + b0) * u0 + tanhf(acc[i][j][1] + b1) * u1;
                rs1 += tanhf(acc[i][j][2] + b0) * u0 + tanhf(acc[i][j][3] + b1) * u1;
            }
            rs0 += __shfl_xor_sync(0xFFFFFFFFu, rs0, 1);
            rs0 += __shfl_xor_sync(0xFFFFFFFFu, rs0, 2);
            rs1 += __shfl_xor_sync(0xFFFFFFFFu, rs1, 1);
            rs1 += __shfl_xor_sync(0xFFFFFFFFu, rs1, 2);
            if (tg == 0) {
                const int r = wm * 32 + i * 16 + g;
                epart[r * 4 + wn]       = rs0;
                epart[(r + 8) * 4 + wn] = rs1;
            }
        }
    }
    __syncthreads();

    // ---- epilogue 2: softmax-numerator weights ----
    float* sWexp = sf + SMEM_WEXP / 4;
    if (tid < TILE_T) {
        const float* epart = sf + SMEM_EP / 4;
        float e = epart[tid * 4 + 0] + epart[tid * 4 + 1] +
                  epart[tid * 4 + 2] + epart[tid * 4 + 3];
        sWexp[tid] = expf(e) * (float)mask[(size_t)b * TLEN + t0 + tid];
    }
    __syncthreads();

    if (tid == 0) {
        float s = 0.f;
        #pragma unroll 8
        for (int m = 0; m < TILE_T; ++m) s += sWexp[m];
        g_S[bt] = s;
    }

    // ---- epilogue 3: weighted column sum from resident fp32 x tile ----
    if (tid < DIM) {
        float a0 = 0.f;
        #pragma unroll 8
        for (int m = 0; m < TILE_T; ++m)
            a0 = fmaf(sWexp[m], xs[m * XSTR + tid], a0);
        g_partial[(size_t)bt * DIM + tid] = a0;
    }

    // ---- fused tail: last CTA of each batch reduces (deterministic order) ----
    __threadfence();
    __syncthreads();
    int* sflag = (int*)(smem + SMEM_FLAG);
    if (tid == 0) {
        int old = atomicAdd(&g_cnt[b], 1);
        *sflag = (old == NTILES - 1);
    }
    __syncthreads();
    if (*sflag) {
        __threadfence();   // acquire: see all tiles' partials
        if (tid < DIM) {
            float s = 0.f, p = 0.f;
            #pragma unroll
            for (int t = 0; t < NTILES; ++t) {
                p += g_partial[(size_t)(b * NTILES + t) * DIM + tid];
                s += g_S[b * NTILES + t];
            }
            out[b * DIM + tid] = p / (s + 1e-7f);
        }
        if (tid == 0) g_cnt[b] = 0;   // reset for next graph replay
    }
}

extern "C" void kernel_launch(void* const* d_in, const int* in_sizes, int n_in,
                              void* d_out, int out_size) {
    const float* x    = (const float*)d_in[0];
    const float* W    = (const float*)d_in[1];
    const float* bvec = (const float*)d_in[2];
    const float* uw   = (const float*)d_in[3];
    const int*   mask = (const int*)d_in[4];
    float* out = (float*)d_out;

    cudaFuncSetAttribute(att_fused, cudaFuncAttributeMaxDynamicSharedMemorySize,
                         SMEM_TOTAL);
    att_fused<<<BATCH * NTILES, 512, SMEM_TOTAL>>>(x, W, bvec, uw, mask, out);
}